// round 16
// baseline (speedup 1.0000x reference)
#include <cuda_runtime.h>
#include <cuda_fp16.h>
#include <math.h>

#define T_ENC  16384
#define HID    512
#define G3     1536
#define VOCAB  31
#define STEPS  100
#define EOS    29
#define NBW    128
#define NT     256
#define NW     (NT/32)          // 8 warps
#define CHUNK  (T_ENC/NBW)      // 128 rows per block
#define RPW    (CHUNK/NW)       // 16 rows per warp
#define SCALE  0.04419417382415922f

#define OUT_LEN (STEPS*VOCAB)
#define OUT_ATT (STEPS*VOCAB+1)

// ---------------- persistent device scratch ----------------
__device__ float4 g_gx2[VOCAB * HID];    // [tok][dim] packed {gxr,gxz,gxn,_}
__device__ float  g_pv[T_ENC * 32];      // PV[j][k] = w_out[k,:512].v_j ; PV[j][31]=1
__device__ float  g_gh[2][G3];           // gh double-buffered by step parity
__device__ float  g_part[2][NBW][32];    // parity-buffered per-block partials
__device__ int    g_flag[NBW];           // per-block monotone publish flags
__device__ int    g_arrive = 0;          // teardown-only rendezvous

// ---------------- smem layout (~93 KB; keys now live in registers) -------
struct __align__(16) SMW {
    float   wout_hi[VOCAB][512];  // w_out[:, 512:]      (62 KB)
    float   whh_s[12][512];       // this block's w_hh rows (24 KB)
    float   whh_b[12];
    float   h[HID];               // fp32 h
    __half2 h2[HID / 2];          // fp16 h
    float   sc[CHUNK];            // e = exp(score) (0 if masked)
    float   zred[NW][32];
    float   tot[NW][32];
    float   a2[32];
};

__device__ __forceinline__ float wsum(float v) {
    #pragma unroll
    for (int o = 16; o; o >>= 1) v += __shfl_xor_sync(0xffffffffu, v, o);
    return v;
}

// per-thread multi-issue poll on one flag word
__device__ __forceinline__ void poll_flag(const int* p, int target) {
    const volatile int* f = (const volatile int*)p;
    for (;;) {
        int v0 = *f; int v1 = *f; int v2 = *f; int v3 = *f;
        if (v0 >= target || v1 >= target || v2 >= target || v3 >= target) break;
    }
}

__device__ __forceinline__ int4 pack8(float4 a, float4 b) {
    __half2 p0 = __floats2half2_rn(a.x, a.y);
    __half2 p1 = __floats2half2_rn(a.z, a.w);
    __half2 p2 = __floats2half2_rn(b.x, b.y);
    __half2 p3 = __floats2half2_rn(b.z, b.w);
    int4 r;
    r.x = *(int*)&p0; r.y = *(int*)&p1; r.z = *(int*)&p2; r.w = *(int*)&p3;
    return r;
}

__global__ void __launch_bounds__(NT, 1)
decoder_kernel(const float* __restrict__ enc,
               const float* __restrict__ embed,
               const float* __restrict__ w_ih,
               const float* __restrict__ w_hh,
               const float* __restrict__ b_ih,
               const float* __restrict__ b_hh,
               const float* __restrict__ w_out,
               const float* __restrict__ b_out,
               float* __restrict__ out)
{
    extern __shared__ __align__(16) unsigned char smem_raw[];
    SMW* sm = (SMW*)smem_raw;

    const int tid  = threadIdx.x;
    const int b    = blockIdx.x;
    const int lane = tid & 31;
    const int warp = tid >> 5;
    const int j0   = b * CHUNK;
    const int rbase = warp * RPW;
    const int d0   = 2 * tid;          // this thread's two h-dims

    // ================= setup =================
    // keys -> REGISTERS (fp16 packed): kreg[r][c] = dims [8*(lane+32c), +8)
    int4 kreg[RPW][2];
    unsigned mbits = 0;
    #pragma unroll
    for (int r = 0; r < RPW; r++) {
        int j = j0 + rbase + r;
        bool anyne = false;
        #pragma unroll
        for (int c = 0; c < 2; c++) {
            const float4* base = (const float4*)(enc + (size_t)j * 1024 + 8 * (lane + 32 * c));
            float4 f0 = __ldg(base);
            float4 f1 = __ldg(base + 1);
            anyne |= (f0.x != 30.f) | (f0.y != 30.f) | (f0.z != 30.f) | (f0.w != 30.f)
                   | (f1.x != 30.f) | (f1.y != 30.f) | (f1.z != 30.f) | (f1.w != 30.f);
            kreg[r][c] = pack8(f0, f1);
        }
        if (__any_sync(0xffffffffu, anyne)) mbits |= (1u << r);
    }
    // PV[j][k] = w_out[k,:512].v_j ; PV[j][31] = 1
    for (int pp = 0; pp < RPW / 2; pp++) {
        int r0 = j0 + rbase + pp * 2;
        float acc0[VOCAB], acc1[VOCAB];
        #pragma unroll
        for (int k = 0; k < VOCAB; k++) { acc0[k] = 0.f; acc1[k] = 0.f; }
        const float* v0p = enc + (size_t)r0 * 1024 + 512;
        const float* v1p = v0p + 1024;
        for (int dd = 0; dd < 512; dd += 32) {
            float v0 = __ldg(v0p + dd + lane);
            float v1 = __ldg(v1p + dd + lane);
            #pragma unroll
            for (int k = 0; k < VOCAB; k++) {
                float w = __ldg(&w_out[(size_t)k * 1024 + dd + lane]);
                acc0[k] += v0 * w;
                acc1[k] += v1 * w;
            }
        }
        #pragma unroll
        for (int k = 0; k < VOCAB; k++) {
            float s0 = wsum(acc0[k]);
            float s1 = wsum(acc1[k]);
            if (lane == 0) {
                g_pv[(size_t)r0 * 32 + k]       = s0;
                g_pv[(size_t)(r0 + 1) * 32 + k] = s1;
            }
        }
        if (lane == 0) {
            g_pv[(size_t)r0 * 32 + 31]       = 1.f;
            g_pv[(size_t)(r0 + 1) * 32 + 31] = 1.f;
        }
    }
    // w_out hi half -> smem
    for (int idx = tid; idx < VOCAB * 512; idx += NT) {
        int k = idx >> 9, d = idx & 511;
        sm->wout_hi[k][d] = w_out[(size_t)k * 1024 + 512 + d];
    }
    // this block's 12 w_hh rows -> smem
    for (int idx = tid; idx < 12 * 512; idx += NT) {
        int rr = idx >> 9, d = idx & 511;
        sm->whh_s[rr][d] = w_hh[(size_t)(b * 12 + rr) * HID + d];
    }
    if (tid < 12) sm->whh_b[tid] = b_hh[b * 12 + tid];
    // gx table portion -> coalesced layout g_gx2[tok*512 + d] = {gxr,gxz,gxn,_}
    {
        int wg = b * NW + warp;
        for (int r = wg; r < G3; r += NBW * NW) {
            const float* wr = w_ih + (size_t)r * HID;
            float wreg[16];
            #pragma unroll
            for (int i = 0; i < 16; i++) wreg[i] = wr[lane + 32 * i];
            float bias = b_ih[r];
            int gate = r >> 9, d = r & 511;
            for (int v = 0; v < VOCAB; v++) {
                const float* er = embed + (size_t)v * HID;
                float acc = 0.f;
                #pragma unroll
                for (int i = 0; i < 16; i++) acc += wreg[i] * er[lane + 32 * i];
                acc = wsum(acc);
                if (lane == 0)
                    ((float*)g_gx2)[((size_t)v * HID + d) * 4 + gate] = acc + bias;
            }
        }
    }
    // gh[0] = b_hh (h0 = 0): block 0 writes it
    if (b == 0)
        for (int i = tid; i < G3; i += NT) __stcg(&g_gh[0][i], b_hh[i]);
    __syncthreads();
    // setup barrier
    if (tid == 0) { __threadfence(); __stcg(&g_flag[b], 1); }
    if (tid < NBW) {
        poll_flag(&g_flag[tid], 1);
        __threadfence();
    }
    __syncthreads();

    // step-invariant registers
    float pv[RPW];
    #pragma unroll
    for (int r = 0; r < RPW; r++)
        pv[r] = __ldcg(&g_pv[(size_t)(j0 + rbase + r) * 32 + lane]);

    // prefetch gh for step 0 (two adjacent dims per thread)
    float2 ghr = *(float2*)&g_gh[0][d0];
    float2 ghz = *(float2*)&g_gh[0][HID + d0];
    float2 ghn = *(float2*)&g_gh[0][2 * HID + d0];

    // ================= decode loop =================
    float h0 = 0.f, h1 = 0.f;
    float av = 0.f, invreg = 0.f;
    int   tok = EOS;
    int   len = STEPS;

    for (int t = 0; t < STEPS; t++) {
        const int p = t & 1, q = p ^ 1;

        // ---- GRU: two dims per thread, gh in regs ----
        {
            float4 ga = __ldg(&g_gx2[tok * HID + d0]);
            float4 gb = __ldg(&g_gx2[tok * HID + d0 + 1]);
            // dim d0
            {
                float r_ = __fdividef(1.f, 1.f + __expf(-(ga.x + ghr.x)));
                float z_ = __fdividef(1.f, 1.f + __expf(-(ga.y + ghz.x)));
                float nx = ga.z + r_ * ghn.x;
                nx = fminf(fmaxf(nx, -15.f), 15.f);
                float t2 = __expf(2.f * nx);
                float n_ = __fdividef(t2 - 1.f, t2 + 1.f);
                h0 = (1.f - z_) * n_ + z_ * h0;
            }
            // dim d0+1
            {
                float r_ = __fdividef(1.f, 1.f + __expf(-(gb.x + ghr.y)));
                float z_ = __fdividef(1.f, 1.f + __expf(-(gb.y + ghz.y)));
                float nx = gb.z + r_ * ghn.y;
                nx = fminf(fmaxf(nx, -15.f), 15.f);
                float t2 = __expf(2.f * nx);
                float n_ = __fdividef(t2 - 1.f, t2 + 1.f);
                h1 = (1.f - z_) * n_ + z_ * h1;
            }
            sm->h[d0]     = h0;
            sm->h[d0 + 1] = h1;
            sm->h2[tid]   = __floats2half2_rn(h0, h1);   // local pack, no shfl
        }
        __syncthreads();

        // ---- gh(t+1): 12 rows; warp w takes rows w and w+8 ----
        for (int rr = warp; rr < 12; rr += NW) {
            float acc = 0.f;
            #pragma unroll
            for (int i = 0; i < 16; i++)
                acc += sm->whh_s[rr][lane + 32 * i] * sm->h[lane + 32 * i];
            acc = wsum(acc);
            if (lane == 0) __stcg(&g_gh[q][b * 12 + rr], acc + sm->whh_b[rr]);
        }

        // ---- scores from REGISTER keys + z accumulation (16 rows/warp) ----
        float zacc = 0.f;
        {
            uint4 u0 = ((const uint4*)sm->h2)[lane];        // c=0
            uint4 u1 = ((const uint4*)sm->h2)[lane + 32];   // c=1
            __half2 ha0 = *(__half2*)&u0.x, ha1 = *(__half2*)&u0.y;
            __half2 ha2 = *(__half2*)&u0.z, ha3 = *(__half2*)&u0.w;
            __half2 hb0 = *(__half2*)&u1.x, hb1 = *(__half2*)&u1.y;
            __half2 hb2 = *(__half2*)&u1.z, hb3 = *(__half2*)&u1.w;

            float acc[RPW];
            #pragma unroll
            for (int r = 0; r < RPW; r++) {
                __half2 s = __hmul2(*(__half2*)&kreg[r][0].x, ha0);
                s = __hfma2(*(__half2*)&kreg[r][0].y, ha1, s);
                s = __hfma2(*(__half2*)&kreg[r][0].z, ha2, s);
                s = __hfma2(*(__half2*)&kreg[r][0].w, ha3, s);
                s = __hfma2(*(__half2*)&kreg[r][1].x, hb0, s);
                s = __hfma2(*(__half2*)&kreg[r][1].y, hb1, s);
                s = __hfma2(*(__half2*)&kreg[r][1].z, hb2, s);
                s = __hfma2(*(__half2*)&kreg[r][1].w, hb3, s);
                float2 f = __half22float2(s);
                acc[r] = f.x + f.y;
            }
            // batched butterfly: 16 independent chains
            #pragma unroll
            for (int o = 16; o; o >>= 1) {
                #pragma unroll
                for (int r = 0; r < RPW; r++)
                    acc[r] += __shfl_xor_sync(0xffffffffu, acc[r], o);
            }
            #pragma unroll
            for (int r = 0; r < RPW; r++) {
                float e = ((mbits >> r) & 1u) ? __expf(acc[r] * SCALE) : 0.f;
                if (lane == r) sm->sc[rbase + r] = e;
                zacc += e * pv[r];
            }
            sm->zred[warp][lane] = zacc;
        }
        __syncthreads();

        // ---- publish partials + flag (warp 0; plain stores) ----
        if (warp == 0) {
            float s = 0.f;
            #pragma unroll
            for (int w = 0; w < NW; w++) s += sm->zred[w][lane];
            __stcg(&g_part[p][b][lane], s);
            __threadfence();
            __syncwarp();
            if (lane == 0) __stcg(&g_flag[b], t + 2);
        }

        // ---- shadow: a2, deferred attn write, capture this step's e ----
        for (int k = warp; k < VOCAB; k += NW) {
            float acc = 0.f;
            #pragma unroll
            for (int i = 0; i < 16; i++)
                acc += sm->wout_hi[k][lane + 32 * i] * sm->h[lane + 32 * i];
            acc = wsum(acc);
            if (lane == 0) sm->a2[k] = acc + __ldg(&b_out[k]);
        }
        if (tid < CHUNK) {
            if (t > 0)
                out[OUT_ATT + (size_t)(t - 1) * T_ENC + j0 + tid] = av * invreg;
            av = sm->sc[tid];
        }

        // ---- wait: 128 threads each poll one block's flag ----
        if (tid < NBW) {
            poll_flag(&g_flag[tid], t + 2);
            __threadfence();
        }
        __syncthreads();

        // ---- prefetch next gh (hides under combine) ----
        float2 ghr_n = *(float2*)&g_gh[q][d0];
        float2 ghz_n = *(float2*)&g_gh[q][HID + d0];
        float2 ghn_n = *(float2*)&g_gh[q][2 * HID + d0];

        // ---- redundant combine (every warp -> tok/inv in regs) ----
        {
            float s = 0.f;
            #pragma unroll
            for (int i = 0; i < RPW; i++)
                s += __ldcg(&g_part[p][warp * RPW + i][lane]);
            sm->tot[warp][lane] = s;
        }
        __syncthreads();
        {
            float s = 0.f;
            #pragma unroll
            for (int g = 0; g < NW; g++) s += sm->tot[g][lane];
            float sg  = __shfl_sync(0xffffffffu, s, 31);
            float inv = __fdividef(1.f, sg);
            invreg = inv;
            float lg  = (lane < VOCAB) ? s * inv + sm->a2[lane] : -3.4e38f;
            float bv = lg; int bi = lane;
            #pragma unroll
            for (int o = 16; o; o >>= 1) {
                float ov = __shfl_xor_sync(0xffffffffu, bv, o);
                int   oi = __shfl_xor_sync(0xffffffffu, bi, o);
                if (ov > bv || (ov == bv && oi < bi)) { bv = ov; bi = oi; }
            }
            tok = bi;                       // identical in every warp/block
            if (b == 0 && warp == 0) {
                if (lane < VOCAB) out[(size_t)t * VOCAB + lane] = lg;
                if (lane == 0) {
                    if (bi == EOS && len == STEPS) len = t;
                }
            }
        }
        ghr = ghr_n; ghz = ghz_n; ghn = ghn_n;
    }

    // final attention row + length
    if (tid < CHUNK)
        out[OUT_ATT + (size_t)(STEPS - 1) * T_ENC + j0 + tid] = av * invreg;
    if (b == 0 && warp == 0 && lane == 0) out[OUT_LEN] = (float)len;

    // ================= teardown: one-shot rendezvous, block0 resets ========
    __syncthreads();
    if (tid == 0) {
        __threadfence();
        atomicAdd(&g_arrive, 1);
        if (b == 0) {
            while (*(volatile int*)&g_arrive < NBW) {}
            for (int i = 0; i < NBW; i++) g_flag[i] = 0;
            __threadfence();
            atomicExch(&g_arrive, 0);
        }
    }
}

extern "C" void kernel_launch(void* const* d_in, const int* in_sizes, int n_in,
                              void* d_out, int out_size) {
    const float* enc    = (const float*)d_in[0];
    const float* embed  = (const float*)d_in[2];
    const float* w_ih   = (const float*)d_in[3];
    const float* w_hh   = (const float*)d_in[4];
    const float* b_ih   = (const float*)d_in[5];
    const float* b_hh   = (const float*)d_in[6];
    const float* w_out  = (const float*)d_in[7];
    const float* b_out  = (const float*)d_in[8];
    float* out = (float*)d_out;

    int smem = (int)sizeof(SMW);
    cudaFuncSetAttribute(decoder_kernel,
                         cudaFuncAttributeMaxDynamicSharedMemorySize, smem);
    decoder_kernel<<<NBW, NT, smem>>>(enc, embed, w_ih, w_hh, b_ih, b_hh,
                                      w_out, b_out, out);
}